// round 1
// baseline (speedup 1.0000x reference)
#include <cuda_runtime.h>
#include <cuda_bf16.h>

#define D_DIM 128
#define MAX_NODES 50000
#define TILE_ROWS 32

__device__ float g_agg[MAX_NODES * D_DIM];
__device__ int g_idx64;

// ---------------------------------------------------------------------------
// Detect whether index arrays are int64 or int32.
// If data is int32, interpreting pairs as int64 gives values with a huge high
// word (next random index in bits 32..63), so the range check fails.
// ---------------------------------------------------------------------------
__global__ void detect_kernel(const void* srcp, int n_edges, int n_nodes) {
    const long long* p = (const long long*)srcp;
    int n = n_edges < 64 ? n_edges : 64;
    int ok = 1;
    for (int i = 0; i < n; i++) {
        long long v = p[i];
        if (v < 0 || v >= (long long)n_nodes) { ok = 0; break; }
    }
    g_idx64 = ok;
}

// ---------------------------------------------------------------------------
// Zero the aggregation buffer (vectorized).
// ---------------------------------------------------------------------------
__global__ void zero_kernel(int n_float4) {
    int i = blockIdx.x * blockDim.x + threadIdx.x;
    float4 z = make_float4(0.f, 0.f, 0.f, 0.f);
    float4* p = (float4*)g_agg;
    for (; i < n_float4; i += gridDim.x * blockDim.x) p[i] = z;
}

// ---------------------------------------------------------------------------
// Scatter: one warp per edge. Coalesced 512B gather of x[src], then
// red.global.add.v4.f32 into g_agg[dst].
// ---------------------------------------------------------------------------
__global__ void scatter_kernel(const float* __restrict__ x,
                               const void* __restrict__ srcp,
                               const void* __restrict__ dstp,
                               int n_edges) {
    int warps_per_block = blockDim.x >> 5;
    int e = blockIdx.x * warps_per_block + (threadIdx.x >> 5);
    if (e >= n_edges) return;
    int lane = threadIdx.x & 31;

    long long s, d;
    if (g_idx64) {
        s = ((const long long*)srcp)[e];
        d = ((const long long*)dstp)[e];
    } else {
        s = (long long)((const int*)srcp)[e];
        d = (long long)((const int*)dstp)[e];
    }

    float4 v = ((const float4*)(x + s * D_DIM))[lane];
    float* out = g_agg + d * D_DIM + lane * 4;
    asm volatile("red.global.add.v4.f32 [%0], {%1,%2,%3,%4};"
                 :: "l"(out), "f"(v.x), "f"(v.y), "f"(v.z), "f"(v.w)
                 : "memory");
}

// ---------------------------------------------------------------------------
// GEMM + ReLU + residual:
//   out[n][j] = relu( sum_k agg[n][k] * W[j][k] ) + x[n][j]
// Block: 256 threads, tile = 32 rows x 128 cols.
// Shared: Ws[k][j] (W transposed, 64KB) + As[k][r] (agg tile transposed, 16KB).
// Each thread: 4 rows x 4 cols register tile, 2x LDS.128 per k-step.
// ---------------------------------------------------------------------------
__global__ __launch_bounds__(256, 2)
void gemm_kernel(const float* __restrict__ x,
                 const float* __restrict__ W,
                 float* __restrict__ out,
                 int n_nodes) {
    extern __shared__ float smem[];
    float* Ws = smem;                    // [128][128]: Ws[k*128 + j] = W[j][k]
    float* As = smem + D_DIM * D_DIM;    // [128][32]:  As[k*32 + r]  = agg[row0+r][k]

    int tid = threadIdx.x;
    int row0 = blockIdx.x * TILE_ROWS;

    // Load W transposed. smem writes coalesced; strided global reads are
    // absorbed by L1 (W = 64KB, fully L1-resident per block).
    #pragma unroll
    for (int i = tid; i < D_DIM * D_DIM; i += 256) {
        int k = i >> 7;        // i = k*128 + j
        int j = i & 127;
        Ws[i] = W[j * D_DIM + k];
    }
    // Load agg tile transposed.
    #pragma unroll
    for (int i = tid; i < TILE_ROWS * D_DIM; i += 256) {
        int k = i >> 5;        // i = k*32 + r
        int r = i & 31;
        int row = row0 + r;
        As[i] = (row < n_nodes) ? g_agg[(long long)row * D_DIM + k] : 0.f;
    }
    __syncthreads();

    int warp = tid >> 5;
    int lane = tid & 31;
    int r0 = warp * 4;     // 8 warps * 4 rows = 32 rows
    int c0 = lane * 4;     // 32 lanes * 4 cols = 128 cols

    float acc[4][4];
    #pragma unroll
    for (int a = 0; a < 4; a++)
        #pragma unroll
        for (int b = 0; b < 4; b++) acc[a][b] = 0.f;

    #pragma unroll 16
    for (int k = 0; k < D_DIM; k++) {
        float4 w4 = *(const float4*)&Ws[k * D_DIM + c0];       // conflict-free
        float4 a4 = *(const float4*)&As[k * TILE_ROWS + r0];   // broadcast
        float av[4] = {a4.x, a4.y, a4.z, a4.w};
        float wv[4] = {w4.x, w4.y, w4.z, w4.w};
        #pragma unroll
        for (int a = 0; a < 4; a++)
            #pragma unroll
            for (int b = 0; b < 4; b++)
                acc[a][b] = fmaf(av[a], wv[b], acc[a][b]);
    }

    // Epilogue: relu + residual, vectorized stores.
    #pragma unroll
    for (int a = 0; a < 4; a++) {
        int row = row0 + r0 + a;
        if (row < n_nodes) {
            long long base = (long long)row * D_DIM + c0;
            float4 xr = *(const float4*)&x[base];
            float4 o;
            o.x = fmaxf(acc[a][0], 0.f) + xr.x;
            o.y = fmaxf(acc[a][1], 0.f) + xr.y;
            o.z = fmaxf(acc[a][2], 0.f) + xr.z;
            o.w = fmaxf(acc[a][3], 0.f) + xr.w;
            *(float4*)&out[base] = o;
        }
    }
}

// ---------------------------------------------------------------------------
extern "C" void kernel_launch(void* const* d_in, const int* in_sizes, int n_in,
                              void* d_out, int out_size) {
    const float* x   = (const float*)d_in[0];
    const void*  src = d_in[1];
    const void*  dst = d_in[2];
    const float* W   = (const float*)d_in[3];
    float* out = (float*)d_out;

    int n_nodes = in_sizes[0] / D_DIM;
    int n_edges = in_sizes[1];

    // GEMM kernel needs 80KB dynamic shared memory.
    static const size_t smem_bytes = (D_DIM * D_DIM + D_DIM * TILE_ROWS) * sizeof(float);
    cudaFuncSetAttribute(gemm_kernel, cudaFuncAttributeMaxDynamicSharedMemorySize,
                         (int)smem_bytes);

    // 1. Detect index dtype (int64 vs silently-downcast int32).
    detect_kernel<<<1, 1>>>(src, n_edges, n_nodes);

    // 2. Zero the aggregation buffer.
    int n_f4 = n_nodes * D_DIM / 4;
    zero_kernel<<<1024, 256>>>(n_f4);

    // 3. Edge scatter (one warp per edge).
    {
        int warps_per_block = 8;            // 256 threads
        int blocks = (n_edges + warps_per_block - 1) / warps_per_block;
        scatter_kernel<<<blocks, warps_per_block * 32>>>(x, src, dst, n_edges);
    }

    // 4. GEMM + ReLU + residual.
    {
        int blocks = (n_nodes + TILE_ROWS - 1) / TILE_ROWS;
        gemm_kernel<<<blocks, 256, smem_bytes>>>(x, W, out, n_nodes);
    }
}

// round 4
// speedup vs baseline: 1.6068x; 1.6068x over previous
#include <cuda_runtime.h>
#include <cuda_bf16.h>

#define D_DIM 128
#define MAX_NODES 50000
#define AS_STRIDE 132   // padded stride for transposed A tile (multiple of 4, not 32)

__device__ float g_agg[MAX_NODES * D_DIM];
__device__ float g_Wt[D_DIM * D_DIM];   // Wt[k][j] = W[j][k]
__device__ int g_idx64;

// ---------------------------------------------------------------------------
// Detect whether index arrays are int64 or int32 (JAX may silently emit i32).
// int32 data read as int64 has garbage high words -> range check fails.
// ---------------------------------------------------------------------------
__global__ void detect_kernel(const void* srcp, int n_edges, int n_nodes) {
    if (threadIdx.x == 0) g_idx64 = 1;
    __syncthreads();
    int n = n_edges < 64 ? n_edges : 64;
    if (threadIdx.x < n) {
        long long v = ((const long long*)srcp)[threadIdx.x];
        if (v < 0 || v >= (long long)n_nodes) g_idx64 = 0;
    }
}

// ---------------------------------------------------------------------------
// Zero the aggregation buffer (vectorized).
// ---------------------------------------------------------------------------
__global__ void zero_kernel(int n_float4) {
    int i = blockIdx.x * blockDim.x + threadIdx.x;
    float4 z = make_float4(0.f, 0.f, 0.f, 0.f);
    float4* p = (float4*)g_agg;
    for (; i < n_float4; i += gridDim.x * blockDim.x) p[i] = z;
}

// ---------------------------------------------------------------------------
// Transpose W [j][k] -> g_Wt [k][j] once per call (standard 32x33 smem tile).
// grid (4,4), block (32,8).
// ---------------------------------------------------------------------------
__global__ void transpose_W_kernel(const float* __restrict__ W) {
    __shared__ float t[32][33];
    int x = blockIdx.x * 32 + threadIdx.x;
    #pragma unroll
    for (int i = threadIdx.y; i < 32; i += 8)
        t[i][threadIdx.x] = W[(blockIdx.y * 32 + i) * D_DIM + x];
    __syncthreads();
    int xo = blockIdx.y * 32 + threadIdx.x;
    #pragma unroll
    for (int i = threadIdx.y; i < 32; i += 8)
        g_Wt[(blockIdx.x * 32 + i) * D_DIM + xo] = t[threadIdx.x][i];
}

// ---------------------------------------------------------------------------
// Scatter: one warp per edge. Coalesced 512B gather of x[src], then
// red.global.add.v4.f32 into g_agg[dst]. L2/LTS-bound (~70us).
// ---------------------------------------------------------------------------
__global__ void scatter_kernel(const float* __restrict__ x,
                               const void* __restrict__ srcp,
                               const void* __restrict__ dstp,
                               int n_edges) {
    int warps_per_block = blockDim.x >> 5;
    int e = blockIdx.x * warps_per_block + (threadIdx.x >> 5);
    if (e >= n_edges) return;
    int lane = threadIdx.x & 31;

    long long s, d;
    if (g_idx64) {
        s = ((const long long*)srcp)[e];
        d = ((const long long*)dstp)[e];
    } else {
        s = (long long)((const int*)srcp)[e];
        d = (long long)((const int*)dstp)[e];
    }

    float4 v = ((const float4*)(x + s * D_DIM))[lane];
    float* out = g_agg + d * D_DIM + lane * 4;
    asm volatile("red.global.add.v4.f32 [%0], {%1,%2,%3,%4};"
                 :: "l"(out), "f"(v.x), "f"(v.y), "f"(v.z), "f"(v.w)
                 : "memory");
}

// ---------------------------------------------------------------------------
// GEMM + ReLU + residual:
//   out[n][j] = relu( sum_k agg[n][k] * W[j][k] ) + x[n][j]
// Block tile: 128 rows x 128 cols, 256 threads (16x16), 8x8 per thread.
// Smem: Ws[k][j] (64KB, from pre-transposed g_Wt, coalesced) +
//       As[k][r] (padded stride 132, ~67KB). 1 CTA/SM.
// Mainloop: 4x LDS.128 per thread per k (64B) feeding 64 FFMA -> 1 B/FMA,
// exactly at the 128 B/cyc smem crossbar cap, overlappable with FMA pipe.
// ---------------------------------------------------------------------------
__global__ __launch_bounds__(256, 1)
void gemm_kernel(const float* __restrict__ x,
                 float* __restrict__ out,
                 int n_nodes) {
    extern __shared__ float smem[];
    float* Ws = smem;                    // [128][128]
    float* As = smem + D_DIM * D_DIM;    // [128][AS_STRIDE]

    int tid = threadIdx.x;
    int row0 = blockIdx.x * 128;

    // Load Wt fully coalesced (read + write both linear).
    #pragma unroll
    for (int i = tid; i < D_DIM * D_DIM; i += 256)
        Ws[i] = g_Wt[i];

    // Load A tile transposed: global reads coalesced, smem writes 4-way
    // conflicted (one-time cost, amortized over 128-k mainloop).
    #pragma unroll
    for (int i = tid; i < 128 * D_DIM; i += 256) {
        int r = i >> 7;
        int k = i & 127;
        int row = row0 + r;
        float v = (row < n_nodes) ? g_agg[(long long)row * D_DIM + k] : 0.f;
        As[k * AS_STRIDE + r] = v;
    }
    __syncthreads();

    int tx = tid & 15;      // 16 col-groups
    int ty = tid >> 4;      // 16 row-groups
    int r0 = ty * 8;
    int c0 = tx * 8;

    float acc[8][8];
    #pragma unroll
    for (int a = 0; a < 8; a++)
        #pragma unroll
        for (int b = 0; b < 8; b++) acc[a][b] = 0.f;

    #pragma unroll 4
    for (int k = 0; k < D_DIM; k++) {
        float4 a0 = *(const float4*)&As[k * AS_STRIDE + r0];
        float4 a1 = *(const float4*)&As[k * AS_STRIDE + r0 + 4];
        float4 w0 = *(const float4*)&Ws[k * D_DIM + c0];
        float4 w1 = *(const float4*)&Ws[k * D_DIM + c0 + 4];
        float av[8] = {a0.x, a0.y, a0.z, a0.w, a1.x, a1.y, a1.z, a1.w};
        float wv[8] = {w0.x, w0.y, w0.z, w0.w, w1.x, w1.y, w1.z, w1.w};
        #pragma unroll
        for (int a = 0; a < 8; a++)
            #pragma unroll
            for (int b = 0; b < 8; b++)
                acc[a][b] = fmaf(av[a], wv[b], acc[a][b]);
    }

    // Epilogue: relu + residual, vectorized.
    #pragma unroll
    for (int a = 0; a < 8; a++) {
        int row = row0 + r0 + a;
        if (row < n_nodes) {
            long long base = (long long)row * D_DIM + c0;
            float4 x0 = *(const float4*)&x[base];
            float4 x1 = *(const float4*)&x[base + 4];
            float4 o0, o1;
            o0.x = fmaxf(acc[a][0], 0.f) + x0.x;
            o0.y = fmaxf(acc[a][1], 0.f) + x0.y;
            o0.z = fmaxf(acc[a][2], 0.f) + x0.z;
            o0.w = fmaxf(acc[a][3], 0.f) + x0.w;
            o1.x = fmaxf(acc[a][4], 0.f) + x1.x;
            o1.y = fmaxf(acc[a][5], 0.f) + x1.y;
            o1.z = fmaxf(acc[a][6], 0.f) + x1.z;
            o1.w = fmaxf(acc[a][7], 0.f) + x1.w;
            *(float4*)&out[base] = o0;
            *(float4*)&out[base + 4] = o1;
        }
    }
}

// ---------------------------------------------------------------------------
extern "C" void kernel_launch(void* const* d_in, const int* in_sizes, int n_in,
                              void* d_out, int out_size) {
    const float* x   = (const float*)d_in[0];
    const void*  src = d_in[1];
    const void*  dst = d_in[2];
    const float* W   = (const float*)d_in[3];
    float* out = (float*)d_out;

    int n_nodes = in_sizes[0] / D_DIM;
    int n_edges = in_sizes[1];

    static const size_t smem_bytes =
        (D_DIM * D_DIM + D_DIM * AS_STRIDE) * sizeof(float);   // ~130KB
    cudaFuncSetAttribute(gemm_kernel, cudaFuncAttributeMaxDynamicSharedMemorySize,
                         (int)smem_bytes);

    // 1. Detect index dtype.
    detect_kernel<<<1, 64>>>(src, n_edges, n_nodes);

    // 2. Zero aggregation buffer; 2b. transpose W (independent, tiny).
    int n_f4 = n_nodes * D_DIM / 4;
    zero_kernel<<<1024, 256>>>(n_f4);
    transpose_W_kernel<<<dim3(4, 4), dim3(32, 8)>>>(W);

    // 3. Edge scatter (one warp per edge).
    {
        int warps_per_block = 8;
        int blocks = (n_edges + warps_per_block - 1) / warps_per_block;
        scatter_kernel<<<blocks, warps_per_block * 32>>>(x, src, dst, n_edges);
    }

    // 4. GEMM + ReLU + residual (128-row tiles).
    {
        int blocks = (n_nodes + 127) / 128;
        gemm_kernel<<<blocks, 256, smem_bytes>>>(x, out, n_nodes);
    }
}